// round 3
// baseline (speedup 1.0000x reference)
#include <cuda_runtime.h>

#define NN 100000
#define NE 1600000
#define SCAN_B 1024
#define NBLK ((NN + SCAN_B - 1) / SCAN_B)   // 98

// ---------------- scratch (static device globals; no runtime allocation) ----
__device__ float g_Hs1[NN * 128];   // (x@W1)*dinv  [N,128]
__device__ float g_h  [NN * 128];   // relu(layer1) [N,128]
__device__ float g_Hs2[NN * 64];    // (h@W2)*dinv  [N,64]
__device__ int   g_count[NN];
__device__ float g_dinv[NN];
__device__ int   g_rowptr[NN + 1];
__device__ int   g_cursor[NN];
__device__ int   g_colidx[NE];
__device__ int   g_partial[128];
__device__ int   g_is64;            // 1 if edge_index is int64, 0 if int32

// ---------------- f32x2 helpers --------------------------------------------
__device__ __forceinline__ unsigned long long pack2(float a, float b) {
    unsigned long long r;
    asm("mov.b64 %0, {%1, %2};" : "=l"(r) : "f"(a), "f"(b));
    return r;
}
__device__ __forceinline__ void fma2(unsigned long long& d,
                                     unsigned long long a,
                                     unsigned long long b) {
    asm("fma.rn.f32x2 %0, %1, %2, %0;" : "+l"(d) : "l"(a), "l"(b));
}
__device__ __forceinline__ float2 unpack2(unsigned long long v) {
    float2 f;
    asm("mov.b64 {%0, %1}, %2;" : "=f"(f.x), "=f"(f.y) : "l"(v));
    return f;
}

// ---------------- edge dtype detection --------------------------------------
// If data is int64 (node ids < 2^31), every odd int32 word is a zero high-word.
// If data is int32, odd words are real src node ids (~all nonzero).
__global__ void k_detect(const int* __restrict__ ei32) {
    __shared__ int s_or;
    if (threadIdx.x == 0) s_or = 0;
    __syncthreads();
    int v = ei32[2 * threadIdx.x + 1];
    if (v != 0) atomicOr(&s_or, 1);
    __syncthreads();
    if (threadIdx.x == 0) g_is64 = (s_or == 0) ? 1 : 0;
}

__device__ __forceinline__ int edge_at(const void* ei, int flag64, int i) {
    return flag64 ? (int)((const long long*)ei)[i] : ((const int*)ei)[i];
}

// ---------------- CSR build -------------------------------------------------
__global__ void k_zero() {
    int i = blockIdx.x * blockDim.x + threadIdx.x;
    if (i < NN) g_count[i] = 0;
}

__global__ void k_hist(const void* __restrict__ ei) {
    int e = blockIdx.x * blockDim.x + threadIdx.x;
    int f64 = g_is64;
    if (e < NE) {
        int d = edge_at(ei, f64, NE + e);
        if ((unsigned)d < (unsigned)NN) atomicAdd(&g_count[d], 1);
    }
}

__global__ void k_scan1() {
    __shared__ int s[SCAN_B];
    int t = threadIdx.x;
    int i = blockIdx.x * SCAN_B + t;
    s[t] = (i < NN) ? g_count[i] : 0;
    __syncthreads();
    for (int off = SCAN_B / 2; off; off >>= 1) {
        if (t < off) s[t] += s[t + off];
        __syncthreads();
    }
    if (t == 0) g_partial[blockIdx.x] = s[0];
}

__global__ void k_scan2() {
    __shared__ int s[128];
    int t = threadIdx.x;
    s[t] = (t < NBLK) ? g_partial[t] : 0;
    __syncthreads();
    if (t == 0) {
        int run = 0;
        for (int b = 0; b < NBLK; b++) { int v = s[b]; s[b] = run; run += v; }
    }
    __syncthreads();
    if (t < NBLK) g_partial[t] = s[t];
}

__global__ void k_scan3() {
    __shared__ int s[SCAN_B];
    int t = threadIdx.x;
    int i = blockIdx.x * SCAN_B + t;
    int v = (i < NN) ? g_count[i] : 0;
    s[t] = v;
    __syncthreads();
    for (int off = 1; off < SCAN_B; off <<= 1) {
        int x = (t >= off) ? s[t - off] : 0;
        __syncthreads();
        s[t] += x;
        __syncthreads();
    }
    int excl = s[t] - v + g_partial[blockIdx.x];
    if (i < NN) {
        g_rowptr[i] = excl;
        g_cursor[i] = excl;
        g_dinv[i]   = rsqrtf((float)(v + 1));
    }
    if (i == NN - 1) g_rowptr[NN] = NE;
}

__global__ void k_scatter(const void* __restrict__ ei) {
    int e = blockIdx.x * blockDim.x + threadIdx.x;
    int f64 = g_is64;
    if (e < NE) {
        int s = edge_at(ei, f64, e);
        int d = edge_at(ei, f64, NE + e);
        if ((unsigned)d < (unsigned)NN && (unsigned)s < (unsigned)NN) {
            int pos = atomicAdd(&g_cursor[d], 1);
            if ((unsigned)pos < (unsigned)NE) g_colidx[pos] = s;
        }
    }
}

// ---------------- GEMM:  out[m, BN] = (A[m, :128] @ W[:128, :BN]) * dinv[m] -
// 64 rows/block, 256 threads = (ty 0..7 -> 8 rows each) x (tx 0..31 -> BN cols)
// A tile in 32KB static smem; W streamed from global (<=64KB, L1-resident).
template <int BN>
__global__ void k_gemm(const float* __restrict__ Ain,
                       const float* __restrict__ W) {
    __shared__ float As[64 * 128];   // 32 KB
    const int tid = threadIdx.x;
    const int tx = tid & 31, ty = tid >> 5;
    const int rowBase = blockIdx.x * 64;

    const float* Ap;
    if constexpr (BN == 128) Ap = Ain; else Ap = (const float*)g_h;

    {   // stage A tile (64x128), float4, guarded
        const float4* A4 = (const float4*)Ap;
        float4* As4 = (float4*)As;
#pragma unroll
        for (int i = 0; i < 8; i++) {
            int f = tid + i * 256;              // 0..2047
            int r = f >> 5, c4 = f & 31;
            int gr = rowBase + r;
            As4[f] = (gr < NN) ? A4[gr * 32 + c4] : make_float4(0.f, 0.f, 0.f, 0.f);
        }
    }
    __syncthreads();

    constexpr int NP = BN / 64;     // u64 lanes per thread along N (2 or 1)
    unsigned long long acc[8][NP];
#pragma unroll
    for (int r = 0; r < 8; r++)
#pragma unroll
        for (int p = 0; p < NP; p++) acc[r][p] = 0ull;

    const float4* As4 = (const float4*)As;

#pragma unroll 4
    for (int k = 0; k < 128; k += 4) {
        unsigned long long breg[4][NP];
#pragma unroll
        for (int kk = 0; kk < 4; kk++) {
            if constexpr (NP == 2) {
                ulonglong2 bb = __ldg(&((const ulonglong2*)W)[(k + kk) * 32 + tx]);
                breg[kk][0] = bb.x; breg[kk][1] = bb.y;
            } else {
                breg[kk][0] = __ldg(&((const unsigned long long*)W)[(k + kk) * 32 + tx]);
            }
        }
#pragma unroll
        for (int r = 0; r < 8; r++) {
            float4 a4 = As4[(ty * 8 + r) * 32 + (k >> 2)];  // LDS.128 broadcast
            unsigned long long aa;
            aa = pack2(a4.x, a4.x);
#pragma unroll
            for (int p = 0; p < NP; p++) fma2(acc[r][p], aa, breg[0][p]);
            aa = pack2(a4.y, a4.y);
#pragma unroll
            for (int p = 0; p < NP; p++) fma2(acc[r][p], aa, breg[1][p]);
            aa = pack2(a4.z, a4.z);
#pragma unroll
            for (int p = 0; p < NP; p++) fma2(acc[r][p], aa, breg[2][p]);
            aa = pack2(a4.w, a4.w);
#pragma unroll
            for (int p = 0; p < NP; p++) fma2(acc[r][p], aa, breg[3][p]);
        }
    }

#pragma unroll
    for (int r = 0; r < 8; r++) {
        int gr = rowBase + ty * 8 + r;
        if (gr < NN) {
            float di = g_dinv[gr];
            if constexpr (BN == 128) {
                float2 f0 = unpack2(acc[r][0]), f1 = unpack2(acc[r][1]);
                ((float4*)g_Hs1)[gr * 32 + tx] =
                    make_float4(f0.x * di, f0.y * di, f1.x * di, f1.y * di);
            } else {
                float2 f0 = unpack2(acc[r][0]);
                ((float2*)g_Hs2)[gr * 32 + tx] = make_float2(f0.x * di, f0.y * di);
            }
        }
    }
}

// ---------------- Aggregation (pull, CSR), one warp per node ----------------
__global__ void k_agg1(const float* __restrict__ b1) {
    int gw = (blockIdx.x * blockDim.x + threadIdx.x) >> 5;   // node id, exact
    int lane = threadIdx.x & 31;
    const float4* __restrict__ Hs = (const float4*)g_Hs1;
    int beg = g_rowptr[gw], end = g_rowptr[gw + 1];
    float4 acc = Hs[gw * 32 + lane];   // self term
    int j = beg;
    while (j < end) {
        int cnt = end - j; if (cnt > 32) cnt = 32;
        int idx = (lane < cnt) ? g_colidx[j + lane] : 0;
        int t = 0;
        for (; t + 4 <= cnt; t += 4) {
            int s0 = __shfl_sync(0xffffffffu, idx, t);
            int s1 = __shfl_sync(0xffffffffu, idx, t + 1);
            int s2 = __shfl_sync(0xffffffffu, idx, t + 2);
            int s3 = __shfl_sync(0xffffffffu, idx, t + 3);
            float4 v0 = Hs[s0 * 32 + lane];
            float4 v1 = Hs[s1 * 32 + lane];
            float4 v2 = Hs[s2 * 32 + lane];
            float4 v3 = Hs[s3 * 32 + lane];
            acc.x += (v0.x + v1.x) + (v2.x + v3.x);
            acc.y += (v0.y + v1.y) + (v2.y + v3.y);
            acc.z += (v0.z + v1.z) + (v2.z + v3.z);
            acc.w += (v0.w + v1.w) + (v2.w + v3.w);
        }
        for (; t < cnt; t++) {
            int s = __shfl_sync(0xffffffffu, idx, t);
            float4 v = Hs[s * 32 + lane];
            acc.x += v.x; acc.y += v.y; acc.z += v.z; acc.w += v.w;
        }
        j += cnt;
    }
    float di = g_dinv[gw];
    float4 bb = ((const float4*)b1)[lane];
    float4 o;
    o.x = fmaxf(fmaf(acc.x, di, bb.x), 0.f);
    o.y = fmaxf(fmaf(acc.y, di, bb.y), 0.f);
    o.z = fmaxf(fmaf(acc.z, di, bb.z), 0.f);
    o.w = fmaxf(fmaf(acc.w, di, bb.w), 0.f);
    ((float4*)g_h)[gw * 32 + lane] = o;
}

__global__ void k_agg2(const float* __restrict__ b2, float* __restrict__ outp) {
    int gw = (blockIdx.x * blockDim.x + threadIdx.x) >> 5;
    int lane = threadIdx.x & 31;
    const float2* __restrict__ Hs = (const float2*)g_Hs2;
    int beg = g_rowptr[gw], end = g_rowptr[gw + 1];
    float2 acc = Hs[gw * 32 + lane];
    int j = beg;
    while (j < end) {
        int cnt = end - j; if (cnt > 32) cnt = 32;
        int idx = (lane < cnt) ? g_colidx[j + lane] : 0;
        int t = 0;
        for (; t + 4 <= cnt; t += 4) {
            int s0 = __shfl_sync(0xffffffffu, idx, t);
            int s1 = __shfl_sync(0xffffffffu, idx, t + 1);
            int s2 = __shfl_sync(0xffffffffu, idx, t + 2);
            int s3 = __shfl_sync(0xffffffffu, idx, t + 3);
            float2 v0 = Hs[s0 * 32 + lane];
            float2 v1 = Hs[s1 * 32 + lane];
            float2 v2 = Hs[s2 * 32 + lane];
            float2 v3 = Hs[s3 * 32 + lane];
            acc.x += (v0.x + v1.x) + (v2.x + v3.x);
            acc.y += (v0.y + v1.y) + (v2.y + v3.y);
        }
        for (; t < cnt; t++) {
            int s = __shfl_sync(0xffffffffu, idx, t);
            float2 v = Hs[s * 32 + lane];
            acc.x += v.x; acc.y += v.y;
        }
        j += cnt;
    }
    float di = g_dinv[gw];
    float2 bb = ((const float2*)b2)[lane];
    ((float2*)outp)[gw * 32 + lane] =
        make_float2(fmaf(acc.x, di, bb.x), fmaf(acc.y, di, bb.y));
}

// ---------------- launch ----------------------------------------------------
extern "C" void kernel_launch(void* const* d_in, const int* in_sizes, int n_in,
                              void* d_out, int out_size) {
    // Identify inputs by element count (all six are distinct).
    const float* x  = 0;
    const float* W1 = 0;
    const float* b1 = 0;
    const float* W2 = 0;
    const float* b2 = 0;
    const void*  ei = 0;
    for (int i = 0; i < n_in; i++) {
        switch (in_sizes[i]) {
            case NN * 128:  x  = (const float*)d_in[i]; break;  // 12,800,000
            case 128 * 128: W1 = (const float*)d_in[i]; break;  // 16,384
            case 128:       b1 = (const float*)d_in[i]; break;
            case 128 * 64:  W2 = (const float*)d_in[i]; break;  // 8,192
            case 64:        b2 = (const float*)d_in[i]; break;
            case 2 * NE:    ei = (const void*)d_in[i];  break;  // 3,200,000
            default: break;
        }
    }

    const int EB = (NE + 255) / 256;          // 6250
    const int GB = (NN + 63) / 64;            // 1563
    const int AB = (NN / 8);                  // 12500 blocks * 8 warps = 100000 nodes

    k_detect<<<1, 256>>>((const int*)ei);
    k_zero<<<(NN + 255) / 256, 256>>>();
    k_hist<<<EB, 256>>>(ei);
    k_scan1<<<NBLK, SCAN_B>>>();
    k_scan2<<<1, 128>>>();
    k_scan3<<<NBLK, SCAN_B>>>();
    k_scatter<<<EB, 256>>>(ei);

    k_gemm<128><<<GB, 256>>>(x, W1);
    k_agg1<<<AB, 256>>>(b1);
    k_gemm<64><<<GB, 256>>>(0, W2);
    k_agg2<<<AB, 256>>>(b2, (float*)d_out);
}